// round 10
// baseline (speedup 1.0000x reference)
#include <cuda_runtime.h>

// cos(pi*t/16) constants
#define CC1 0.98078528040323044913f
#define CC2 0.92387953251128675613f
#define CC3 0.83146961230254523708f
#define CC4 0.70710678118654752440f
#define CC5 0.55557023301960222474f
#define CC6 0.38268343236508977173f
#define CC7 0.19509032201612826785f

typedef unsigned long long u64;

__device__ __forceinline__ u64 pack2(float lo, float hi) {
    u64 r; asm("mov.b64 %0, {%1, %2};" : "=l"(r) : "f"(lo), "f"(hi)); return r;
}
__device__ __forceinline__ void unpack2(u64 v, float& lo, float& hi) {
    asm("mov.b64 {%0, %1}, %2;" : "=f"(lo), "=f"(hi) : "l"(v));
}
__device__ __forceinline__ u64 add2(u64 a, u64 b) {
    u64 d; asm("add.rn.f32x2 %0, %1, %2;" : "=l"(d) : "l"(a), "l"(b)); return d;
}
__device__ __forceinline__ u64 mul2(u64 a, u64 b) {
    u64 d; asm("mul.rn.f32x2 %0, %1, %2;" : "=l"(d) : "l"(a), "l"(b)); return d;
}
__device__ __forceinline__ u64 fma2(u64 a, u64 b, u64 c) {
    u64 d; asm("fma.rn.f32x2 %0, %1, %2, %3;" : "=l"(d) : "l"(a), "l"(b), "l"(c)); return d;
}
__device__ __forceinline__ u64 shflx64(u64 v) {
    return (u64)__shfl_xor_sync(0xffffffffu, (long long)v, 1);
}

// Packed accumulate with compile-time sign over both column-pair halves.
#define ACC2(A01, A23, X01, X23, K, P) do {                                        \
    if (SGN[K][P] > 0) {                                                           \
        (A01) = fma2((X01), PCC[IDX[K][P]], (A01));                                \
        (A23) = fma2((X23), PCC[IDX[K][P]], (A23));                                \
    } else {                                                                       \
        (A01) = fma2(mul2((X01), PCC[IDX[K][P]]), MIN1, (A01));                    \
        (A23) = fma2(mul2((X23), PCC[IDX[K][P]]), MIN1, (A23));                    \
    }                                                                              \
} while (0)

// Horizontal masked DCT round trip for one row, 2 lanes per tile.
// Lane holds 4 columns as (A01, A23). Forward partial over 4 local cols,
// TWO coefficients packed per 64-bit shfl_xor(1) reduce, then packed
// back-substitution. Wp carries the 0.25 scale (fwd+back => 1/16);
// l==0 uses raw sum forward and 0.03125 backward.
template <unsigned MASK>
__device__ __forceinline__ void hrow(u64& A01, u64& A23,
                                     const u64 (&Wp01)[6], const u64 (&Wp23)[6],
                                     u64 P03125)
{
    float pr[6];
#pragma unroll
    for (int l = 0; l < 6; ++l) {
        if ((MASK >> l) & 1) {
            u64 t = (l == 0) ? add2(A01, A23)
                             : fma2(A23, Wp23[l], mul2(A01, Wp01[l]));
            float x, y; unpack2(t, x, y);
            pr[l] = x + y;
        }
    }
    // kept-coefficient list (folds at compile time under full unroll)
    int K[6]; int n = 0;
#pragma unroll
    for (int l = 0; l < 6; ++l) if ((MASK >> l) & 1) { K[n] = l; ++n; }
    // pairwise packed cross-lane reduce
#pragma unroll
    for (int i = 0; i + 1 < n; i += 2) {
        u64 P = pack2(pr[K[i]], pr[K[i + 1]]);
        P = add2(P, shflx64(P));
        unpack2(P, pr[K[i]], pr[K[i + 1]]);
    }
    if (n & 1) pr[K[n - 1]] += __shfl_xor_sync(0xffffffffu, pr[K[n - 1]], 1);
    // packed back-substitution
    u64 s01 = 0ull, s23 = 0ull;
#pragma unroll
    for (int i = 0; i < n; ++i) {
        const int l = K[i];
        u64 Bb = pack2(pr[l], pr[l]);
        u64 w01 = (l == 0) ? P03125 : Wp01[l];
        u64 w23 = (l == 0) ? P03125 : Wp23[l];
        if (i == 0) { s01 = mul2(Bb, w01); s23 = mul2(Bb, w23); }
        else        { s01 = fma2(Bb, w01, s01); s23 = fma2(Bb, w23, s23); }
    }
    A01 = s01; A23 = s23;
}

// Two threads per 8x8 tile: lane h = g&1 owns columns 4h..4h+3 as two f32x2.
// Luma split: out_c = T9(x_c) + DeltaT16(y); no output color conversion.
// All three stages packed (FFMA2); stage 2 uses 1-round packed-pair shuffles.
__global__ void __launch_bounds__(128, 4)
jpeg_fused_kernel(const float* __restrict__ in, float* __restrict__ out, int nthr)
{
    const int g = blockIdx.x * blockDim.x + threadIdx.x;
    if (g >= nthr) return;
    const int tile = g >> 1;
    const int h = g & 1;

    // D[k][n] = cos(pi/8 * (n+0.5) * k)
    const float D[8][8] = {
        { 1.f,  1.f,  1.f,  1.f,  1.f,  1.f,  1.f,  1.f},
        { CC1,  CC3,  CC5,  CC7, -CC7, -CC5, -CC3, -CC1},
        { CC2,  CC6, -CC6, -CC2, -CC2, -CC6,  CC6,  CC2},
        { CC3, -CC7, -CC1, -CC5,  CC5,  CC1,  CC7, -CC3},
        { CC4, -CC4, -CC4,  CC4,  CC4, -CC4, -CC4,  CC4},
        { CC5, -CC1,  CC7,  CC3, -CC3, -CC7,  CC1, -CC5},
        { CC6, -CC2,  CC2, -CC6, -CC6,  CC2, -CC2,  CC6},
        { CC7, -CC5,  CC3, -CC1,  CC1, -CC3,  CC5, -CC7}
    };
    // |D[k][p]| = CC_{IDX[k][p]}, sign = SGN[k][p], p = 0..3
    const int IDX[7][4] = {
        {0,0,0,0}, {1,3,5,7}, {2,6,6,2}, {3,7,1,5}, {4,4,4,4}, {5,1,7,3}, {6,2,2,6}
    };
    const int SGN[7][4] = {
        {1,1,1,1}, {1,1,1,1}, {1,1,-1,-1}, {1,-1,-1,-1}, {1,-1,-1,1}, {1,-1,1,1}, {1,-1,1,-1}
    };
    const float CCv[8] = {1.f, CC1, CC2, CC3, CC4, CC5, CC6, CC7};

    u64 PCC[8];
#pragma unroll
    for (int i = 1; i < 8; ++i) PCC[i] = pack2(CCv[i], CCv[i]);
    const u64 MIN1   = pack2(-1.f, -1.f);
    const u64 P03125 = pack2(0.03125f, 0.03125f);
    const u64 PHALF  = pack2(0.5f, 0.5f);
    const u64 PCR    = pack2(0.299f, 0.299f);
    const u64 PCG    = pack2(0.587f, 0.587f);
    const u64 PCB    = pack2(0.114f, 0.114f);

    const int W = 512;
    const int S = 512 * 512;

    const int b  = tile >> 12;
    const int t  = tile & 4095;
    const int ty = t >> 6;
    const int tx = t & 63;

    const size_t off = (size_t)b * (3 * S) + (size_t)(ty * 8) * W
                     + (size_t)(tx * 8) + (size_t)(h * 4);
    const float* p0 = in + off;
    float* o0 = out + off;

    // Packed accumulators: luma rows 0-6, R/G/B rows 0-2; (01, 23) column pairs
    u64 AY01[7], AY23[7];
    u64 AR01[3], AR23[3], AG01[3], AG23[3], AB01[3], AB23[3];
#pragma unroll
    for (int k = 0; k < 7; ++k) { AY01[k] = 0ull; AY23[k] = 0ull; }
#pragma unroll
    for (int k = 0; k < 3; ++k) {
        AR01[k] = 0ull; AR23[k] = 0ull;
        AG01[k] = 0ull; AG23[k] = 0ull;
        AB01[k] = 0ull; AB23[k] = 0ull;
    }

    // ---- stage 1: row pairs (p, 7-p): packed s/d, packed luma, packed accumulate ----
#pragma unroll
    for (int p = 0; p < 4; ++p) {
        const int i0 = p * W;
        const int i1 = (7 - p) * W;

        ulonglong2 ra = *(const ulonglong2*)(p0 + i0);
        ulonglong2 rb = *(const ulonglong2*)(p0 + i1);
        u64 sr01 = add2(ra.x, rb.x), sr23 = add2(ra.y, rb.y);
        u64 dr01 = fma2(rb.x, MIN1, ra.x), dr23 = fma2(rb.y, MIN1, ra.y);

        ulonglong2 ga = *(const ulonglong2*)(p0 + i0 + S);
        ulonglong2 gb = *(const ulonglong2*)(p0 + i1 + S);
        u64 sg01 = add2(ga.x, gb.x), sg23 = add2(ga.y, gb.y);
        u64 dg01 = fma2(gb.x, MIN1, ga.x), dg23 = fma2(gb.y, MIN1, ga.y);

        ulonglong2 ba = *(const ulonglong2*)(p0 + i0 + 2 * S);
        ulonglong2 bb = *(const ulonglong2*)(p0 + i1 + 2 * S);
        u64 sb01 = add2(ba.x, bb.x), sb23 = add2(ba.y, bb.y);
        u64 db01 = fma2(bb.x, MIN1, ba.x), db23 = fma2(bb.y, MIN1, ba.y);

        // packed luma of s and d
        u64 sy01 = fma2(PCR, sr01, fma2(PCG, sg01, mul2(PCB, sb01)));
        u64 sy23 = fma2(PCR, sr23, fma2(PCG, sg23, mul2(PCB, sb23)));
        u64 dy01 = fma2(PCR, dr01, fma2(PCG, dg01, mul2(PCB, db01)));
        u64 dy23 = fma2(PCR, dr23, fma2(PCG, dg23, mul2(PCB, db23)));

        // luma rows 0-6 (even <- s, odd <- d)
        AY01[0] = add2(AY01[0], sy01); AY23[0] = add2(AY23[0], sy23);
        ACC2(AY01[2], AY23[2], sy01, sy23, 2, p);
        ACC2(AY01[4], AY23[4], sy01, sy23, 4, p);
        ACC2(AY01[6], AY23[6], sy01, sy23, 6, p);
        ACC2(AY01[1], AY23[1], dy01, dy23, 1, p);
        ACC2(AY01[3], AY23[3], dy01, dy23, 3, p);
        ACC2(AY01[5], AY23[5], dy01, dy23, 5, p);
        // RGB rows 0-2
        AR01[0] = add2(AR01[0], sr01); AR23[0] = add2(AR23[0], sr23);
        ACC2(AR01[2], AR23[2], sr01, sr23, 2, p);
        ACC2(AR01[1], AR23[1], dr01, dr23, 1, p);
        AG01[0] = add2(AG01[0], sg01); AG23[0] = add2(AG23[0], sg23);
        ACC2(AG01[2], AG23[2], sg01, sg23, 2, p);
        ACC2(AG01[1], AG23[1], dg01, dg23, 1, p);
        AB01[0] = add2(AB01[0], sb01); AB23[0] = add2(AB23[0], sb23);
        ACC2(AB01[2], AB23[2], sb01, sb23, 2, p);
        ACC2(AB01[1], AB23[1], db01, db23, 1, p);
    }

    // Lane-dependent packed horizontal weights, 0.25-scaled (built after stage 1
    // to keep stage-1 register peak down).
    u64 Wp01[6], Wp23[6];
#pragma unroll
    for (int l = 1; l < 6; ++l) {
        Wp01[l] = h ? pack2(0.25f * D[l][4], 0.25f * D[l][5])
                    : pack2(0.25f * D[l][0], 0.25f * D[l][1]);
        Wp23[l] = h ? pack2(0.25f * D[l][6], 0.25f * D[l][7])
                    : pack2(0.25f * D[l][2], 0.25f * D[l][3]);
    }

    // ---- stage 2: horizontal masked round trip ----
    // luma-delta masks per row: {4,5},{3,4},{2,3},{0-3},{0-2},{0,1},{0}
    hrow<0x30u>(AY01[0], AY23[0], Wp01, Wp23, P03125);
    hrow<0x18u>(AY01[1], AY23[1], Wp01, Wp23, P03125);
    hrow<0x0Cu>(AY01[2], AY23[2], Wp01, Wp23, P03125);
    hrow<0x0Fu>(AY01[3], AY23[3], Wp01, Wp23, P03125);
    hrow<0x07u>(AY01[4], AY23[4], Wp01, Wp23, P03125);
    hrow<0x03u>(AY01[5], AY23[5], Wp01, Wp23, P03125);
    hrow<0x01u>(AY01[6], AY23[6], Wp01, Wp23, P03125);
    // RGB (UV-mask) rows: prefixes {4,3,2}
    hrow<0x0Fu>(AR01[0], AR23[0], Wp01, Wp23, P03125);
    hrow<0x07u>(AR01[1], AR23[1], Wp01, Wp23, P03125);
    hrow<0x03u>(AR01[2], AR23[2], Wp01, Wp23, P03125);
    hrow<0x0Fu>(AG01[0], AG23[0], Wp01, Wp23, P03125);
    hrow<0x07u>(AG01[1], AG23[1], Wp01, Wp23, P03125);
    hrow<0x03u>(AG01[2], AG23[2], Wp01, Wp23, P03125);
    hrow<0x0Fu>(AB01[0], AB23[0], Wp01, Wp23, P03125);
    hrow<0x07u>(AB01[1], AB23[1], Wp01, Wp23, P03125);
    hrow<0x03u>(AB01[2], AB23[2], Wp01, Wp23, P03125);

    // Row-0 vertical-inverse weight is 0.5 relative to D-rows: halve once.
    AY01[0] = mul2(AY01[0], PHALF); AY23[0] = mul2(AY23[0], PHALF);
    AR01[0] = mul2(AR01[0], PHALF); AR23[0] = mul2(AR23[0], PHALF);
    AG01[0] = mul2(AG01[0], PHALF); AG23[0] = mul2(AG23[0], PHALF);
    AB01[0] = mul2(AB01[0], PHALF); AB23[0] = mul2(AB23[0], PHALF);

    // ---- stage 3: packed even/odd vertical inverse; out_c = idct(A_c) + idct(AY) ----
#pragma unroll
    for (int p = 0; p < 4; ++p) {
        const int i0 = p * W;
        const int i1 = (7 - p) * W;

        u64 e01 = AY01[0], e23 = AY23[0];
        ACC2(e01, e23, AY01[2], AY23[2], 2, p);
        ACC2(e01, e23, AY01[4], AY23[4], 4, p);
        ACC2(e01, e23, AY01[6], AY23[6], 6, p);
        u64 o01 = mul2(AY01[1], PCC[IDX[1][p]]);   // SGN[1][p] always +
        u64 o23 = mul2(AY23[1], PCC[IDX[1][p]]);
        ACC2(o01, o23, AY01[3], AY23[3], 3, p);
        ACC2(o01, o23, AY01[5], AY23[5], 5, p);
        const u64 yA01 = add2(e01, o01), yA23 = add2(e23, o23);
        const u64 yB01 = fma2(o01, MIN1, e01), yB23 = fma2(o23, MIN1, e23);

        u64 ce01, ce23, co01, co23;
        ulonglong2 v;

        ce01 = AR01[0]; ce23 = AR23[0];
        ACC2(ce01, ce23, AR01[2], AR23[2], 2, p);
        co01 = mul2(AR01[1], PCC[IDX[1][p]]); co23 = mul2(AR23[1], PCC[IDX[1][p]]);
        v.x = add2(add2(ce01, co01), yA01); v.y = add2(add2(ce23, co23), yA23);
        *(ulonglong2*)(o0 + i0) = v;
        v.x = add2(fma2(co01, MIN1, ce01), yB01); v.y = add2(fma2(co23, MIN1, ce23), yB23);
        *(ulonglong2*)(o0 + i1) = v;

        ce01 = AG01[0]; ce23 = AG23[0];
        ACC2(ce01, ce23, AG01[2], AG23[2], 2, p);
        co01 = mul2(AG01[1], PCC[IDX[1][p]]); co23 = mul2(AG23[1], PCC[IDX[1][p]]);
        v.x = add2(add2(ce01, co01), yA01); v.y = add2(add2(ce23, co23), yA23);
        *(ulonglong2*)(o0 + i0 + S) = v;
        v.x = add2(fma2(co01, MIN1, ce01), yB01); v.y = add2(fma2(co23, MIN1, ce23), yB23);
        *(ulonglong2*)(o0 + i1 + S) = v;

        ce01 = AB01[0]; ce23 = AB23[0];
        ACC2(ce01, ce23, AB01[2], AB23[2], 2, p);
        co01 = mul2(AB01[1], PCC[IDX[1][p]]); co23 = mul2(AB23[1], PCC[IDX[1][p]]);
        v.x = add2(add2(ce01, co01), yA01); v.y = add2(add2(ce23, co23), yA23);
        *(ulonglong2*)(o0 + i0 + 2 * S) = v;
        v.x = add2(fma2(co01, MIN1, ce01), yB01); v.y = add2(fma2(co23, MIN1, ce23), yB23);
        *(ulonglong2*)(o0 + i1 + 2 * S) = v;
    }
}

extern "C" void kernel_launch(void* const* d_in, const int* in_sizes, int n_in,
                              void* d_out, int out_size)
{
    const float* in = (const float*)d_in[0];
    float* out = (float*)d_out;
    const int total = in_sizes[0];               // B*3*512*512
    const int B = total / (3 * 512 * 512);
    const int nthr = B * 64 * 64 * 2;            // 2 threads per tile
    const int threads = 128;
    const int blocks = (nthr + threads - 1) / threads;
    jpeg_fused_kernel<<<blocks, threads>>>(in, out, nthr);
}